// round 10
// baseline (speedup 1.0000x reference)
#include <cuda_runtime.h>

// ---------------------------------------------------------------------------
// Masked multi-level MSE loss (B=16, C=256, T=128, S in {80,40,20}):
//   L = mean_l [ sum((M_l * (p_l - t_l))^2) / (C * sum(M_l)) ]
//
// SINGLE fused kernel, one wave of 740 blocks (148 SMs x 5):
//   1) each block rasterizes all 128 boxes as row-spans (atomicOr) into a
//      16.8KB SMEM bit mask (1 bit/cell, linear cell order, 3 levels packed).
//   2) streams all levels with per-thread grid-stride over single f4 units
//      (maximal interleave -> balanced); nibble mask from SMEM (LDS);
//      warp-ballot skip: a warp's 32 units = 128 consecutive cells, so
//      all-zero warps (~5-8%) skip their loads coherently.
//   3) last block (ticket) computes counts by popc over its own SMEM mask
//      and finalizes into d_out. Ticket self-resets for graph replay.
// ---------------------------------------------------------------------------

#define NB 16
#define NT 128
#define NC 256
#define GRID_BLOCKS 740
#define BT 256
#define TTOT (GRID_BLOCKS * BT)    // 189440

// bit-mask words: lvl0 16*200, lvl1 16*50, lvl2 16*13 (last half-word padded)
#define NWORDS 4208
#define OFF0 0u
#define OFF1 3200u
#define OFF2 4000u
#define W0 200u
#define W1 50u
#define W2 13u

__device__ float g_pa[3][GRID_BLOCKS];
__device__ unsigned g_ticket = 0;

// ---------------------------------------------------------------------------
__device__ __forceinline__ float block_sum_f(float v, float* sm) {
#pragma unroll
    for (int o = 16; o; o >>= 1) v += __shfl_down_sync(0xffffffffu, v, o);
    const int lane = threadIdx.x & 31, warp = threadIdx.x >> 5;
    if (lane == 0) sm[warp] = v;
    __syncthreads();
    v = (threadIdx.x < (BT / 32)) ? sm[threadIdx.x] : 0.f;
    if (warp == 0) {
#pragma unroll
        for (int o = 16; o; o >>= 1) v += __shfl_down_sync(0xffffffffu, v, o);
    }
    __syncthreads();
    return v;
}

__device__ __forceinline__ int block_sum_i(int v, int* sm) {
#pragma unroll
    for (int o = 16; o; o >>= 1) v += __shfl_down_sync(0xffffffffu, v, o);
    const int lane = threadIdx.x & 31, warp = threadIdx.x >> 5;
    if (lane == 0) sm[warp] = v;
    __syncthreads();
    v = (threadIdx.x < (BT / 32)) ? sm[threadIdx.x] : 0;
    if (warp == 0) {
#pragma unroll
        for (int o = 16; o; o >>= 1) v += __shfl_down_sync(0xffffffffu, v, o);
    }
    __syncthreads();
    return v;
}

// ---------------------------------------------------------------------------
// Rasterize one box into the SMEM bit mask at one level (row spans, atomicOr).
__device__ __forceinline__ void raster_box(unsigned* sbits, unsigned base,
                                           int S, int xl, int xr, int yt, int yd) {
#pragma unroll 1
    for (int y = yt; y <= yd; y++) {
        const int c0 = y * S + xl, c1 = y * S + xr;
        const int w0 = c0 >> 5, w1 = c1 >> 5;
        const unsigned m0 = 0xFFFFFFFFu << (c0 & 31);
        const unsigned m1 = 0xFFFFFFFFu >> (31 - (c1 & 31));
        if (w0 == w1) {
            atomicOr(&sbits[base + w0], m0 & m1);
        } else {
            atomicOr(&sbits[base + w0], m0);
            for (int w = w0 + 1; w < w1; w++)
                atomicOr(&sbits[base + w], 0xFFFFFFFFu);
            atomicOr(&sbits[base + w1], m1);
        }
    }
}

// ---------------------------------------------------------------------------
// Stream one level: grid-stride over single f4 units, unroll x2 with
// warp-ballot skip (warp-uniform branches).
template <int S>
__device__ __forceinline__ float level_sum(const float4* __restrict__ p,
                                           const float4* __restrict__ q,
                                           const unsigned* __restrict__ sbits,
                                           unsigned OFF, unsigned W,
                                           unsigned gid) {
    constexpr unsigned CH4 = (unsigned)S * (S / 4);   // f4 per channel image
    constexpr unsigned KCH = (unsigned)NC * CH4;      // f4 per batch
    constexpr unsigned U   = (unsigned)NB * KCH;      // total f4
    constexpr unsigned T   = (unsigned)TTOT;

    float acc0 = 0.f, acc1 = 0.f;
    unsigned i = gid;

#pragma unroll 1
    for (; i + T < U; i += 2u * T) {
        const unsigned i1 = i + T;
        const unsigned b0 = i  / KCH, r0 = i  % CH4;
        const unsigned b1 = i1 / KCH, r1 = i1 % CH4;
        const unsigned n0 = (sbits[OFF + b0 * W + (r0 >> 3)] >> ((r0 & 7u) * 4u)) & 0xFu;
        const unsigned n1 = (sbits[OFF + b1 * W + (r1 >> 3)] >> ((r1 & 7u) * 4u)) & 0xFu;
        const unsigned act0 = __ballot_sync(0xffffffffu, n0 != 0u);
        const unsigned act1 = __ballot_sync(0xffffffffu, n1 != 0u);
        if (act0) {
            const float fm0 = __uint_as_float(( n0       & 1u) * 0x3F800000u);
            const float fm1 = __uint_as_float(((n0 >> 1) & 1u) * 0x3F800000u);
            const float fm2 = __uint_as_float(((n0 >> 2) & 1u) * 0x3F800000u);
            const float fm3 = __uint_as_float(((n0 >> 3) & 1u) * 0x3F800000u);
            const float4 a = __ldg(p + i);
            const float4 c = __ldg(q + i);
            float d, e;
            d = a.x - c.x; e = fm0 * d; acc0 = fmaf(e, d, acc0);
            d = a.y - c.y; e = fm1 * d; acc1 = fmaf(e, d, acc1);
            d = a.z - c.z; e = fm2 * d; acc0 = fmaf(e, d, acc0);
            d = a.w - c.w; e = fm3 * d; acc1 = fmaf(e, d, acc1);
        }
        if (act1) {
            const float fm0 = __uint_as_float(( n1       & 1u) * 0x3F800000u);
            const float fm1 = __uint_as_float(((n1 >> 1) & 1u) * 0x3F800000u);
            const float fm2 = __uint_as_float(((n1 >> 2) & 1u) * 0x3F800000u);
            const float fm3 = __uint_as_float(((n1 >> 3) & 1u) * 0x3F800000u);
            const float4 a = __ldg(p + i1);
            const float4 c = __ldg(q + i1);
            float d, e;
            d = a.x - c.x; e = fm0 * d; acc0 = fmaf(e, d, acc0);
            d = a.y - c.y; e = fm1 * d; acc1 = fmaf(e, d, acc1);
            d = a.z - c.z; e = fm2 * d; acc0 = fmaf(e, d, acc0);
            d = a.w - c.w; e = fm3 * d; acc1 = fmaf(e, d, acc1);
        }
    }
#pragma unroll 1
    for (; i < U; i += T) {
        const unsigned b0 = i / KCH, r0 = i % CH4;
        const unsigned n0 = (sbits[OFF + b0 * W + (r0 >> 3)] >> ((r0 & 7u) * 4u)) & 0xFu;
        const unsigned act0 = __ballot_sync(0xffffffffu, n0 != 0u);
        if (act0) {
            const float fm0 = __uint_as_float(( n0       & 1u) * 0x3F800000u);
            const float fm1 = __uint_as_float(((n0 >> 1) & 1u) * 0x3F800000u);
            const float fm2 = __uint_as_float(((n0 >> 2) & 1u) * 0x3F800000u);
            const float fm3 = __uint_as_float(((n0 >> 3) & 1u) * 0x3F800000u);
            const float4 a = __ldg(p + i);
            const float4 c = __ldg(q + i);
            float d, e;
            d = a.x - c.x; e = fm0 * d; acc0 = fmaf(e, d, acc0);
            d = a.y - c.y; e = fm1 * d; acc1 = fmaf(e, d, acc1);
            d = a.z - c.z; e = fm2 * d; acc0 = fmaf(e, d, acc0);
            d = a.w - c.w; e = fm3 * d; acc1 = fmaf(e, d, acc1);
        }
    }
    return acc0 + acc1;
}

// ---------------------------------------------------------------------------
__global__ void __launch_bounds__(BT, 5)
fused_kernel(const float4* __restrict__ p0, const float4* __restrict__ t0,
             const float4* __restrict__ p1, const float4* __restrict__ t1,
             const float4* __restrict__ p2, const float4* __restrict__ t2,
             const float* __restrict__ bboxes,
             const int* __restrict__ batch_idx,
             float* __restrict__ out) {
    __shared__ unsigned sbits[NWORDS];
    __shared__ float smf[32];
    __shared__ int smi[32];

    // ---- build bit mask in SMEM ----
    for (int w = threadIdx.x; w < NWORDS; w += BT) sbits[w] = 0u;
    __syncthreads();
    if (threadIdx.x < NT) {
        const int t = threadIdx.x;
        const int b = batch_idx[t];
        const float4 bb = ((const float4*)bboxes)[t];
#pragma unroll
        for (int lvl = 0; lvl < 3; lvl++) {
            const int S = (lvl == 0) ? 80 : (lvl == 1) ? 40 : 20;
            const unsigned base = (lvl == 0) ? (OFF0 + (unsigned)b * W0)
                                : (lvl == 1) ? (OFF1 + (unsigned)b * W1)
                                             : (OFF2 + (unsigned)b * W2);
            const float fS = (float)S;
            const int xc = (int)floorf(bb.x * fS);
            const int yc = (int)floorf(bb.y * fS);
            const int w  = (int)floorf(bb.z * fS);
            const int h  = (int)floorf(bb.w * fS);
            const int xl = max(xc - w / 2, 0);
            const int yt = max(yc - h / 2, 0);
            const int xr = min(xc + w / 2, S - 1);
            const int yd = min(yc + h / 2, S - 1);
            raster_box(sbits, base, S, xl, xr, yt, yd);
        }
    }
    __syncthreads();

    // ---- stream all three levels ----
    const unsigned gid = blockIdx.x * BT + threadIdx.x;
    float a0 = level_sum<80>(p0, t0, sbits, OFF0, W0, gid);
    float a1 = level_sum<40>(p1, t1, sbits, OFF1, W1, gid);
    float a2 = level_sum<20>(p2, t2, sbits, OFF2, W2, gid);

    a0 = block_sum_f(a0, smf);
    a1 = block_sum_f(a1, smf);
    a2 = block_sum_f(a2, smf);

    __shared__ bool s_last;
    if (threadIdx.x == 0) {
        g_pa[0][blockIdx.x] = a0;
        g_pa[1][blockIdx.x] = a1;
        g_pa[2][blockIdx.x] = a2;
        __threadfence();
        unsigned n = atomicAdd(&g_ticket, 1u);
        s_last = (n == GRID_BLOCKS - 1);
    }
    __syncthreads();
    if (!s_last) return;

    // ---- finalize (last block only; uses its own SMEM mask for counts) ----
    float fa0 = 0.f, fa1 = 0.f, fa2 = 0.f;
    for (int i = threadIdx.x; i < GRID_BLOCKS; i += BT) {
        fa0 += g_pa[0][i]; fa1 += g_pa[1][i]; fa2 += g_pa[2][i];
    }
    int fc0 = 0, fc1 = 0, fc2 = 0;
    for (int w = threadIdx.x; w < NWORDS; w += BT) {
        const int pc = __popc(sbits[w]);
        if (w < (int)OFF1)      fc0 += pc;
        else if (w < (int)OFF2) fc1 += pc;
        else                    fc2 += pc;
    }
    fa0 = block_sum_f(fa0, smf);
    fa1 = block_sum_f(fa1, smf);
    fa2 = block_sum_f(fa2, smf);
    fc0 = block_sum_i(fc0, smi);
    fc1 = block_sum_i(fc1, smi);
    fc2 = block_sum_i(fc2, smi);

    if (threadIdx.x == 0) {
        double L = (double)fa0 / (256.0 * (double)fc0) +
                   (double)fa1 / (256.0 * (double)fc1) +
                   (double)fa2 / (256.0 * (double)fc2);
        out[0] = (float)(L / 3.0);
        __threadfence();
        g_ticket = 0;   // restore for next graph replay
    }
}

// ---------------------------------------------------------------------------
extern "C" void kernel_launch(void* const* d_in, const int* in_sizes, int n_in,
                              void* d_out, int out_size) {
    // input order: pred0, true0, pred1, true1, pred2, true2, bboxes, batch_idx, cls
    const float4* p0 = (const float4*)d_in[0];
    const float4* t0 = (const float4*)d_in[1];
    const float4* p1 = (const float4*)d_in[2];
    const float4* t1 = (const float4*)d_in[3];
    const float4* p2 = (const float4*)d_in[4];
    const float4* t2 = (const float4*)d_in[5];
    const float* bboxes = (const float*)d_in[6];
    const int* batch_idx = (const int*)d_in[7];

    fused_kernel<<<GRID_BLOCKS, BT>>>(p0, t0, p1, t1, p2, t2,
                                      bboxes, batch_idx, (float*)d_out);
}